// round 3
// baseline (speedup 1.0000x reference)
#include <cuda_runtime.h>
#include <math_constants.h>
#include <cstdint>

#define BATCH   8
#define NPTS    2048
#define BN      16384        // BATCH*NPTS
#define KNN     20
#define EPSV    1e-5f
#define SLOPE   0.2f

// ---------------- scratch (device globals; no allocation APIs) ----------------
__device__ float g_dist[(size_t)BATCH * NPTS * NPTS];     // 128 MB
__device__ int   g_nbr [(size_t)BN * KNN];                // global row idx of neighbors
__device__ float g_edge[(size_t)BN * KNN * 256];          // 335 MB (max O=256)
__device__ float g_cent[(size_t)BN * 256];                // 16 MB
__device__ float g_xcat[(size_t)BN * 512];                // concat [x1|x2|x3|x4]
__device__ float g_xx  [BN];
__device__ float g_h5  [(size_t)BN * 512];
__device__ float g_hmax[BATCH * 512];

// ---------------- squared row norms ----------------
__global__ void xx_kernel(const float* __restrict__ Aext, int asel, int lda, int offa, int C) {
    int p = blockIdx.x * blockDim.x + threadIdx.x;
    if (p >= BN) return;
    const float* A = asel ? g_xcat : Aext;
    const float* r = A + (size_t)p * lda + offa;
    float s = 0.f;
    for (int c = 0; c < C; c++) s += r[c] * r[c];
    g_xx[p] = s;
}

// ---------------- pairwise neg-sqdist GEMM: D = 2*X.X^T - xx_i - xx_j ----------------
// grid (32,32,8), block 256
__global__ __launch_bounds__(256, 2)
void dist_gemm(const float* __restrict__ Aext, int asel, int lda, int offa, int K) {
    __shared__ float As[16][64];
    __shared__ float Bs[16][64];
    const float* A = asel ? g_xcat : Aext;
    int bz = blockIdx.z;
    int i0 = blockIdx.x * 64;
    int j0 = blockIdx.y * 64;
    int base = bz * NPTS;
    const float* Xb = A + (size_t)base * lda + offa;
    int tid = threadIdx.x;
    int ty = tid >> 4, tx = tid & 15;
    float acc[4][4] = {};
    for (int k0 = 0; k0 < K; k0 += 16) {
        #pragma unroll
        for (int q = 0; q < 4; q++) {
            int idx = tid * 4 + q;              // 0..1023
            int m = idx >> 4, kk = idx & 15;
            int k = k0 + kk;
            As[kk][m] = (k < K) ? Xb[(size_t)(i0 + m) * lda + k] : 0.f;
            Bs[kk][m] = (k < K) ? Xb[(size_t)(j0 + m) * lda + k] : 0.f;
        }
        __syncthreads();
        #pragma unroll
        for (int kk = 0; kk < 16; kk++) {
            float a[4], b[4];
            #pragma unroll
            for (int i = 0; i < 4; i++) a[i] = As[kk][ty * 4 + i];
            #pragma unroll
            for (int j = 0; j < 4; j++) b[j] = Bs[kk][tx * 4 + j];
            #pragma unroll
            for (int i = 0; i < 4; i++)
                #pragma unroll
                for (int j = 0; j < 4; j++) acc[i][j] += a[i] * b[j];
        }
        __syncthreads();
    }
    float* outb = g_dist + (size_t)bz * NPTS * NPTS;
    #pragma unroll
    for (int i = 0; i < 4; i++) {
        int gi = i0 + ty * 4 + i;
        float xi = g_xx[base + gi];
        #pragma unroll
        for (int j = 0; j < 4; j++) {
            int gj = j0 + tx * 4 + j;
            outb[(size_t)gi * NPTS + gj] = 2.f * acc[i][j] - xi - g_xx[base + gj];
        }
    }
}

// ---------------- top-20 per row (warp per row, 20 argmax passes in smem) ----------------
// grid 4096, block 128
__global__ __launch_bounds__(128)
void topk_kernel() {
    __shared__ float sd[4][NPTS];
    int w = threadIdx.x >> 5, lane = threadIdx.x & 31;
    int row = blockIdx.x * 4 + w;           // 0..16383
    const float* dr = g_dist + (size_t)row * NPTS;
    for (int j = lane; j < NPTS; j += 32) sd[w][j] = dr[j];
    __syncwarp();
    int b = row >> 11;
    for (int t = 0; t < KNN; t++) {
        float bv = -CUDART_INF_F; int bi = 0;
        for (int j = lane; j < NPTS; j += 32) {
            float v = sd[w][j];
            if (v > bv || (v == bv && j < bi)) { bv = v; bi = j; }
        }
        #pragma unroll
        for (int off = 16; off; off >>= 1) {
            float ov = __shfl_xor_sync(0xffffffffu, bv, off);
            int   oi = __shfl_xor_sync(0xffffffffu, bi, off);
            if (ov > bv || (ov == bv && oi < bi)) { bv = ov; bi = oi; }
        }
        if (lane == 0) {
            g_nbr[(size_t)row * KNN + t] = (b << 11) + bi;
            sd[w][bi] = -CUDART_INF_F;
        }
        __syncwarp();
    }
}

// ---------------- generic NT GEMM: out[m,o] = sum_k A'[m,k] * W[o, offb+k] ----------------
// A'[m,k] = gather ? (A[nbr[m],k] - A[m/20,k]) : A[m,k]
// out_sel: 0 -> g_edge, 1 -> g_cent, 2 -> g_h5
// epi: 0 plain, 1 bn+leakyrelu
__global__ __launch_bounds__(256, 2)
void gemm_w(const float* __restrict__ Aext, int asel, int lda, int offa, int use_gather,
            const float* __restrict__ W, int ldb, int offb,
            int out_sel, int ldo,
            int M, int K, int O,
            int epi, const float* __restrict__ gg, const float* __restrict__ bb) {
    __shared__ float As[16][64];
    __shared__ float Bs[16][64];
    const float* A = asel ? g_xcat : Aext;
    float* out = (out_sel == 0) ? g_edge : (out_sel == 1) ? g_cent : g_h5;
    int m0 = blockIdx.x * 64;
    int o0 = blockIdx.y * 64;
    int tid = threadIdx.x;
    int ty = tid >> 4, tx = tid & 15;
    float acc[4][4] = {};
    for (int k0 = 0; k0 < K; k0 += 16) {
        #pragma unroll
        for (int q = 0; q < 4; q++) {
            int idx = tid * 4 + q;
            int mloc = idx >> 4, kk = idx & 15;
            int k = k0 + kk;
            int m = m0 + mloc;
            float av = 0.f;
            if (k < K && m < M) {
                if (use_gather) {
                    int nb  = g_nbr[m];
                    int ctr = m / KNN;
                    av = A[(size_t)nb * lda + offa + k] - A[(size_t)ctr * lda + offa + k];
                } else {
                    av = A[(size_t)m * lda + offa + k];
                }
            }
            As[kk][mloc] = av;
            int o = o0 + mloc;
            Bs[kk][mloc] = (k < K && o < O) ? W[(size_t)o * ldb + offb + k] : 0.f;
        }
        __syncthreads();
        #pragma unroll
        for (int kk = 0; kk < 16; kk++) {
            float a[4], b[4];
            #pragma unroll
            for (int i = 0; i < 4; i++) a[i] = As[kk][ty * 4 + i];
            #pragma unroll
            for (int j = 0; j < 4; j++) b[j] = Bs[kk][tx * 4 + j];
            #pragma unroll
            for (int i = 0; i < 4; i++)
                #pragma unroll
                for (int j = 0; j < 4; j++) acc[i][j] += a[i] * b[j];
        }
        __syncthreads();
    }
    #pragma unroll
    for (int i = 0; i < 4; i++) {
        int m = m0 + ty * 4 + i;
        if (m >= M) continue;
        #pragma unroll
        for (int j = 0; j < 4; j++) {
            int o = o0 + tx * 4 + j;
            if (o >= O) continue;
            float v = acc[i][j];
            if (epi == 1) {
                float s = gg[o] * rsqrtf(1.f + EPSV);
                v = v * s + bb[o];
                v = (v >= 0.f) ? v : SLOPE * v;
            }
            out[(size_t)m * ldo + o] = v;
        }
    }
}

// ---------------- per-point: max_k lrelu((edge+cent)*s + b) -> xcat slice ----------------
// grid BN, block 128
__global__ void edge_reduce(const float* __restrict__ gg, const float* __restrict__ bb,
                            int O, int offo) {
    int p = blockIdx.x;
    float inv = rsqrtf(1.f + EPSV);
    for (int o = threadIdx.x; o < O; o += blockDim.x) {
        float s = gg[o] * inv;
        float bv = bb[o];
        float cent = g_cent[(size_t)p * O + o];
        const float* eh = g_edge + ((size_t)p * KNN) * O + o;
        float mx = -CUDART_INF_F;
        #pragma unroll
        for (int k = 0; k < KNN; k++) {
            float h = (eh[(size_t)k * O] + cent) * s + bv;
            h = (h >= 0.f) ? h : SLOPE * h;
            mx = fmaxf(mx, h);
        }
        g_xcat[(size_t)p * 512 + offo + o] = mx;
    }
}

// ---------------- global max over n + write feat ----------------
__global__ void maxn_kernel(float* __restrict__ out) {
    int gid = blockIdx.x * blockDim.x + threadIdx.x;   // 0..4095
    if (gid >= BATCH * 512) return;
    int b = gid >> 9, o = gid & 511;
    const float* base = g_h5 + (size_t)b * NPTS * 512 + o;
    float mx = -CUDART_INF_F;
    for (int n = 0; n < NPTS; n++) mx = fmaxf(mx, base[(size_t)n * 512]);
    g_hmax[gid] = mx;
    out[gid] = mx;                                      // feat (B,1,512)
}

// ---------------- embedding = h @ Wemb^T ----------------
__global__ void emb_kernel(const float* __restrict__ Wemb, float* __restrict__ out) {
    int gid = blockIdx.x * blockDim.x + threadIdx.x;   // 0..2047
    if (gid >= BATCH * 256) return;
    int b = gid >> 8, oe = gid & 255;
    const float* h = g_hmax + b * 512;
    const float* w = Wemb + (size_t)oe * 512;
    float s = 0.f;
    for (int c = 0; c < 512; c++) s += h[c] * w[c];
    out[BATCH * 512 + gid] = s;
}

// ---------------- driver ----------------
static void run_layer(const float* Aext, int asel, int lda, int offa, int C,
                      const float* W, const float* gg, const float* bb,
                      int O, int offo) {
    // kNN on this layer's input
    xx_kernel<<<BN / 256, 256>>>(Aext, asel, lda, offa, C);
    dist_gemm<<<dim3(NPTS / 64, NPTS / 64, BATCH), 256>>>(Aext, asel, lda, offa, C);
    topk_kernel<<<BN / 4, 128>>>();
    // edge GEMM (gathered differences vs W[:, 0:C])
    int Me = BN * KNN;
    gemm_w<<<dim3((Me + 63) / 64, O / 64), 256>>>(Aext, asel, lda, offa, 1,
                                                  W, 2 * C, 0,
                                                  0 /*g_edge*/, O,
                                                  Me, C, O, 0, nullptr, nullptr);
    // central GEMM (x_i vs W[:, C:2C])
    gemm_w<<<dim3(BN / 64, O / 64), 256>>>(Aext, asel, lda, offa, 0,
                                           W, 2 * C, C,
                                           1 /*g_cent*/, O,
                                           BN, C, O, 0, nullptr, nullptr);
    // bn + lrelu + max over k  -> xcat slice
    edge_reduce<<<BN, 128>>>(gg, bb, O, offo);
}

extern "C" void kernel_launch(void* const* d_in, const int* in_sizes, int n_in,
                              void* d_out, int out_size) {
    const float* x    = (const float*)d_in[0];
    const float* W1   = (const float*)d_in[1];
    const float* g1   = (const float*)d_in[2];
    const float* b1   = (const float*)d_in[3];
    const float* W2   = (const float*)d_in[4];
    const float* g2   = (const float*)d_in[5];
    const float* b2   = (const float*)d_in[6];
    const float* W3   = (const float*)d_in[7];
    const float* g3   = (const float*)d_in[8];
    const float* b3   = (const float*)d_in[9];
    const float* W4   = (const float*)d_in[10];
    const float* g4   = (const float*)d_in[11];
    const float* b4   = (const float*)d_in[12];
    const float* W5   = (const float*)d_in[13];
    const float* g5   = (const float*)d_in[14];
    const float* b5   = (const float*)d_in[15];
    const float* Wemb = (const float*)d_in[16];
    float* out = (float*)d_out;

    // Edge conv layers; outputs packed into g_xcat columns [0:64|64:128|128:256|256:512]
    run_layer(x,       0, 3,   0,   3,   W1, g1, b1, 64,  0);
    run_layer(nullptr, 1, 512, 0,   64,  W2, g2, b2, 64,  64);
    run_layer(nullptr, 1, 512, 64,  64,  W3, g3, b3, 128, 128);
    run_layer(nullptr, 1, 512, 128, 128, W4, g4, b4, 256, 256);

    // W5 MLP with bn+lrelu epilogue
    gemm_w<<<dim3(BN / 64, 512 / 64), 256>>>(nullptr, 1, 512, 0, 0,
                                             W5, 512, 0,
                                             2 /*g_h5*/, 512,
                                             BN, 512, 512, 1, g5, b5);
    // global max over points -> feat, then embedding
    maxn_kernel<<<16, 256>>>(out);
    emb_kernel<<<8, 256>>>(Wemb, out);
}

// round 6
// speedup vs baseline: 1.1995x; 1.1995x over previous
#include <cuda_runtime.h>
#include <math_constants.h>
#include <cstdint>

#define BATCH   8
#define NPTS    2048
#define BNT     16384        // BATCH*NPTS
#define KNN     20
#define EPSV    1e-5f
#define SLOPE   0.2f

// ---------------- scratch (device globals; no allocation APIs) ----------------
__device__ float g_dist[(size_t)BATCH * NPTS * NPTS];     // 128 MB
__device__ int   g_nbr [(size_t)BNT * KNN];
__device__ float g_cent[(size_t)BNT * 256];
__device__ float g_xcat[(size_t)BNT * 512];
__device__ float g_xx  [BNT];
__device__ float g_h5  [(size_t)BNT * 512];
__device__ float g_hmax[BATCH * 512];

// ---------------- squared row norms ----------------
__global__ void xx_kernel(const float* __restrict__ Aext, int asel, int lda, int offa, int C) {
    int p = blockIdx.x * blockDim.x + threadIdx.x;
    if (p >= BNT) return;
    const float* A = asel ? g_xcat : Aext;
    const float* r = A + (size_t)p * lda + offa;
    float s = 0.f;
    for (int c = 0; c < C; c++) s += r[c] * r[c];
    g_xx[p] = s;
}

// ---------------- pairwise neg-sqdist GEMM, symmetric: 128x128 tile, 8x8 micro ----------------
// grid (16,16,8), block 256; blocks with j0<i0 exit; off-diagonal write both triangles
__global__ __launch_bounds__(256, 2)
void dist_gemm2(const float* __restrict__ Aext, int asel, int lda, int offa, int K) {
    __shared__ float As[16][136];
    __shared__ float Bs[16][136];
    int i0 = blockIdx.x * 128, j0 = blockIdx.y * 128;
    if (j0 < i0) return;
    const float* A = asel ? g_xcat : Aext;
    int base = blockIdx.z * NPTS;
    const float* Xb = A + (size_t)base * lda + offa;
    int tid = threadIdx.x, ty = tid >> 4, tx = tid & 15;
    float acc[8][8] = {};
    for (int k0 = 0; k0 < K; k0 += 16) {
        #pragma unroll
        for (int q = 0; q < 8; q++) {
            int e = q * 256 + tid;
            int r = e >> 4, kk = e & 15;
            int k = k0 + kk;
            As[kk][r] = (k < K) ? Xb[(size_t)(i0 + r) * lda + k] : 0.f;
            Bs[kk][r] = (k < K) ? Xb[(size_t)(j0 + r) * lda + k] : 0.f;
        }
        __syncthreads();
        #pragma unroll
        for (int kk = 0; kk < 16; kk++) {
            float4 a0 = *(const float4*)&As[kk][ty * 8];
            float4 a1 = *(const float4*)&As[kk][ty * 8 + 4];
            float4 b0 = *(const float4*)&Bs[kk][tx * 8];
            float4 b1 = *(const float4*)&Bs[kk][tx * 8 + 4];
            float a[8] = {a0.x, a0.y, a0.z, a0.w, a1.x, a1.y, a1.z, a1.w};
            float b[8] = {b0.x, b0.y, b0.z, b0.w, b1.x, b1.y, b1.z, b1.w};
            #pragma unroll
            for (int i = 0; i < 8; i++)
                #pragma unroll
                for (int j = 0; j < 8; j++) acc[i][j] += a[i] * b[j];
        }
        __syncthreads();
    }
    float* outb = g_dist + (size_t)blockIdx.z * NPTS * NPTS;
    float xi[8], xj[8];
    #pragma unroll
    for (int i = 0; i < 8; i++) xi[i] = g_xx[base + i0 + ty * 8 + i];
    #pragma unroll
    for (int j = 0; j < 8; j++) xj[j] = g_xx[base + j0 + tx * 8 + j];
    bool mirror = (j0 > i0);
    #pragma unroll
    for (int i = 0; i < 8; i++) {
        int gi = i0 + ty * 8 + i;
        #pragma unroll
        for (int j = 0; j < 8; j++) {
            int gj = j0 + tx * 8 + j;
            float v = 2.f * acc[i][j] - xi[i] - xj[j];
            outb[(size_t)gi * NPTS + gj] = v;
            if (mirror) outb[(size_t)gj * NPTS + gi] = v;
        }
    }
}

// ---------------- top-20 per row (warp per row, 20 argmax passes in smem) ----------------
__global__ __launch_bounds__(128)
void topk_kernel() {
    __shared__ float sd[4][NPTS];
    int w = threadIdx.x >> 5, lane = threadIdx.x & 31;
    int row = blockIdx.x * 4 + w;
    const float* dr = g_dist + (size_t)row * NPTS;
    for (int j = lane; j < NPTS; j += 32) sd[w][j] = dr[j];
    __syncwarp();
    int b = row >> 11;
    for (int t = 0; t < KNN; t++) {
        float bv = -CUDART_INF_F; int bi = 0;
        for (int j = lane; j < NPTS; j += 32) {
            float v = sd[w][j];
            if (v > bv || (v == bv && j < bi)) { bv = v; bi = j; }
        }
        #pragma unroll
        for (int off = 16; off; off >>= 1) {
            float ov = __shfl_xor_sync(0xffffffffu, bv, off);
            int   oi = __shfl_xor_sync(0xffffffffu, bi, off);
            if (ov > bv || (ov == bv && oi < bi)) { bv = ov; bi = oi; }
        }
        if (lane == 0) {
            g_nbr[(size_t)row * KNN + t] = (b << 11) + bi;
            sd[w][bi] = -CUDART_INF_F;
        }
        __syncwarp();
    }
}

// ---------------- plain GEMM: out[m,o] = sum_k A[m,k+offa] * W[o, offb+k] ----------------
// 128xBN tile, 8x(BN/16) micro, 256 thr. out_sel: 1 -> g_cent (ldo), 2 -> g_h5 (ldo=512)
template<int BN, int TN>
__global__ __launch_bounds__(256, 2)
void plain_gemm(const float* __restrict__ Aext, int asel, int lda, int offa,
                const float* __restrict__ W, int ldb, int offb,
                int out_sel, int ldo, int K,
                int epi, const float* __restrict__ gg, const float* __restrict__ bb) {
    __shared__ float As[16][136];
    __shared__ float Bs[16][BN + 8];
    const float* A = asel ? g_xcat : Aext;
    float* out = (out_sel == 1) ? g_cent : g_h5;
    int m0 = blockIdx.x * 128;
    int o0 = blockIdx.y * BN;
    int tid = threadIdx.x, ty = tid >> 4, tx = tid & 15;
    float acc[8][TN] = {};
    for (int k0 = 0; k0 < K; k0 += 16) {
        #pragma unroll
        for (int q = 0; q < 8; q++) {
            int e = q * 256 + tid;
            int r = e >> 4, kk = e & 15;
            int k = k0 + kk;
            As[kk][r] = (k < K) ? A[(size_t)(m0 + r) * lda + offa + k] : 0.f;
        }
        #pragma unroll
        for (int q = 0; q < BN / 16; q++) {
            int e = q * 256 + tid;
            int r = e >> 4, kk = e & 15;
            int k = k0 + kk;
            Bs[kk][r] = (k < K) ? W[(size_t)(o0 + r) * ldb + offb + k] : 0.f;
        }
        __syncthreads();
        #pragma unroll
        for (int kk = 0; kk < 16; kk++) {
            float4 a0 = *(const float4*)&As[kk][ty * 8];
            float4 a1 = *(const float4*)&As[kk][ty * 8 + 4];
            float a[8] = {a0.x, a0.y, a0.z, a0.w, a1.x, a1.y, a1.z, a1.w};
            float b[TN];
            #pragma unroll
            for (int h = 0; h < TN / 4; h++) {
                float4 t = *(const float4*)&Bs[kk][tx * TN + h * 4];
                b[h * 4] = t.x; b[h * 4 + 1] = t.y; b[h * 4 + 2] = t.z; b[h * 4 + 3] = t.w;
            }
            #pragma unroll
            for (int i = 0; i < 8; i++)
                #pragma unroll
                for (int j = 0; j < TN; j++) acc[i][j] += a[i] * b[j];
        }
        __syncthreads();
    }
    float inv = rsqrtf(1.f + EPSV);
    #pragma unroll
    for (int i = 0; i < 8; i++) {
        int m = m0 + ty * 8 + i;
        #pragma unroll
        for (int j = 0; j < TN; j++) {
            int o = o0 + tx * TN + j;
            float v = acc[i][j];
            if (epi) {
                float s = gg[o] * inv;
                v = v * s + bb[o];
                v = (v >= 0.f) ? v : SLOPE * v;
            }
            out[(size_t)m * ldo + o] = v;
        }
    }
}

// ---------------- fused edge GEMM: BM=160 (8 points x 20 edges) ----------------
// acc[m,o] = sum_k (A[nbr[m],k]-A[ctr,k]) * W[o,k]; epilogue: +cent, bn, lrelu, max over 20,
// write g_xcat[p*512 + offo + o]. micro 10 x TN; point = 2 consecutive ty = 1 warp.
template<int BN, int TN>
__global__ __launch_bounds__(256, 2)
void edge_gemm_fused(const float* __restrict__ Aext, int asel, int lda, int offa,
                     const float* __restrict__ W, int ldb,
                     int K, int O, int offo,
                     const float* __restrict__ gg, const float* __restrict__ bb) {
    __shared__ float As[16][168];
    __shared__ float Bs[16][BN + 8];
    __shared__ int s_nbr[160];
    const float* A = asel ? g_xcat : Aext;
    int m0 = blockIdx.x * 160;
    int o0 = blockIdx.y * BN;
    int tid = threadIdx.x, ty = tid >> 4, tx = tid & 15;
    if (tid < 160) s_nbr[tid] = g_nbr[m0 + tid];
    __syncthreads();
    float acc[10][TN] = {};
    for (int k0 = 0; k0 < K; k0 += 16) {
        #pragma unroll
        for (int q = 0; q < 10; q++) {
            int e = q * 256 + tid;
            int r = e >> 4, kk = e & 15;
            int k = k0 + kk;
            float v = 0.f;
            if (k < K) {
                int nb  = s_nbr[r];
                int ctr = m0 / 20 + r / 20;
                v = A[(size_t)nb * lda + offa + k] - A[(size_t)ctr * lda + offa + k];
            }
            As[kk][r] = v;
        }
        #pragma unroll
        for (int q = 0; q < BN / 16; q++) {
            int e = q * 256 + tid;
            int r = e >> 4, kk = e & 15;
            int k = k0 + kk;
            Bs[kk][r] = (k < K) ? W[(size_t)(o0 + r) * ldb + k] : 0.f;
        }
        __syncthreads();
        #pragma unroll
        for (int kk = 0; kk < 16; kk++) {
            float a[10];
            #pragma unroll
            for (int h = 0; h < 5; h++) {
                float2 t = *(const float2*)&As[kk][ty * 10 + h * 2];
                a[h * 2] = t.x; a[h * 2 + 1] = t.y;
            }
            float b[TN];
            #pragma unroll
            for (int h = 0; h < TN / 4; h++) {
                float4 t = *(const float4*)&Bs[kk][tx * TN + h * 4];
                b[h * 4] = t.x; b[h * 4 + 1] = t.y; b[h * 4 + 2] = t.z; b[h * 4 + 3] = t.w;
            }
            #pragma unroll
            for (int i = 0; i < 10; i++)
                #pragma unroll
                for (int j = 0; j < TN; j++) acc[i][j] += a[i] * b[j];
        }
        __syncthreads();
    }
    // epilogue: point p spans ty=2w,2w+1 (one warp)
    int p = m0 / 20 + (ty >> 1);
    float inv = rsqrtf(1.f + EPSV);
    #pragma unroll
    for (int j = 0; j < TN; j++) {
        int o = o0 + tx * TN + j;
        float cent = g_cent[(size_t)p * O + o];
        float s = gg[o] * inv;
        float bv = bb[o];
        float mx = -CUDART_INF_F;
        #pragma unroll
        for (int i = 0; i < 10; i++) {
            float h = (acc[i][j] + cent) * s + bv;
            h = (h >= 0.f) ? h : SLOPE * h;
            mx = fmaxf(mx, h);
        }
        mx = fmaxf(mx, __shfl_xor_sync(0xffffffffu, mx, 16));
        if ((ty & 1) == 0) g_xcat[(size_t)p * 512 + offo + o] = mx;
    }
}

// ---------------- global max over n + write feat ----------------
__global__ void maxn_kernel(float* __restrict__ out) {
    int gid = blockIdx.x * blockDim.x + threadIdx.x;
    if (gid >= BATCH * 512) return;
    int b = gid >> 9, o = gid & 511;
    const float* base = g_h5 + (size_t)b * NPTS * 512 + o;
    float mx = -CUDART_INF_F;
    for (int n = 0; n < NPTS; n++) mx = fmaxf(mx, base[(size_t)n * 512]);
    g_hmax[gid] = mx;
    out[gid] = mx;
}

// ---------------- embedding = h @ Wemb^T ----------------
__global__ void emb_kernel(const float* __restrict__ Wemb, float* __restrict__ out) {
    int gid = blockIdx.x * blockDim.x + threadIdx.x;
    if (gid >= BATCH * 256) return;
    int b = gid >> 8, oe = gid & 255;
    const float* h = g_hmax + b * 512;
    const float* w = Wemb + (size_t)oe * 512;
    float s = 0.f;
    for (int c = 0; c < 512; c++) s += h[c] * w[c];
    out[BATCH * 512 + gid] = s;
}

// ---------------- driver ----------------
static void run_layer(const float* Aext, int asel, int lda, int offa, int C,
                      const float* W, const float* gg, const float* bb,
                      int O, int offo) {
    xx_kernel<<<BNT / 256, 256>>>(Aext, asel, lda, offa, C);
    dist_gemm2<<<dim3(16, 16, 8), 256>>>(Aext, asel, lda, offa, C);
    topk_kernel<<<BNT / 4, 128>>>();
    // central GEMM: x_i vs W[:, C:2C] -> g_cent (row stride O)
    if (O == 64)
        plain_gemm<64, 4><<<dim3(128, 1), 256>>>(Aext, asel, lda, offa,
                                                 W, 2 * C, C, 1, O, C, 0, nullptr, nullptr);
    else
        plain_gemm<128, 8><<<dim3(128, O / 128), 256>>>(Aext, asel, lda, offa,
                                                        W, 2 * C, C, 1, O, C, 0, nullptr, nullptr);
    // fused edge GEMM + bn + lrelu + max_k -> g_xcat slice
    if (O == 64)
        edge_gemm_fused<64, 4><<<dim3(2048, 1), 256>>>(Aext, asel, lda, offa,
                                                       W, 2 * C, C, O, offo, gg, bb);
    else
        edge_gemm_fused<128, 8><<<dim3(2048, O / 128), 256>>>(Aext, asel, lda, offa,
                                                              W, 2 * C, C, O, offo, gg, bb);
}

extern "C" void kernel_launch(void* const* d_in, const int* in_sizes, int n_in,
                              void* d_out, int out_size) {
    const float* x    = (const float*)d_in[0];
    const float* W1   = (const float*)d_in[1];
    const float* g1   = (const float*)d_in[2];
    const float* b1   = (const float*)d_in[3];
    const float* W2   = (const float*)d_in[4];
    const float* g2   = (const float*)d_in[5];
    const float* b2   = (const float*)d_in[6];
    const float* W3   = (const float*)d_in[7];
    const float* g3   = (const float*)d_in[8];
    const float* b3   = (const float*)d_in[9];
    const float* W4   = (const float*)d_in[10];
    const float* g4   = (const float*)d_in[11];
    const float* b4   = (const float*)d_in[12];
    const float* W5   = (const float*)d_in[13];
    const float* g5   = (const float*)d_in[14];
    const float* b5   = (const float*)d_in[15];
    const float* Wemb = (const float*)d_in[16];
    float* out = (float*)d_out;

    run_layer(x,       0, 3,   0,   3,   W1, g1, b1, 64,  0);
    run_layer(nullptr, 1, 512, 0,   64,  W2, g2, b2, 64,  64);
    run_layer(nullptr, 1, 512, 64,  64,  W3, g3, b3, 128, 128);
    run_layer(nullptr, 1, 512, 128, 128, W4, g4, b4, 256, 256);

    // W5 MLP with bn+lrelu epilogue -> g_h5
    plain_gemm<128, 8><<<dim3(128, 4), 256>>>(nullptr, 1, 512, 0,
                                              W5, 512, 0, 2, 512, 512, 1, g5, b5);
    maxn_kernel<<<16, 256>>>(out);
    emb_kernel<<<8, 256>>>(Wemb, out);
}

// round 9
// speedup vs baseline: 1.5989x; 1.3329x over previous
#include <cuda_runtime.h>
#include <math_constants.h>
#include <cstdint>

#define BATCH   8
#define NPTS    2048
#define BNT     16384        // BATCH*NPTS
#define KNN     20
#define EPSV    1e-5f
#define SLOPE   0.2f

// ---------------- scratch (device globals; no allocation APIs) ----------------
__device__ float g_dist[(size_t)BATCH * NPTS * NPTS];     // 128 MB
__device__ int   g_nbr [(size_t)BNT * KNN];
__device__ float g_feat[(size_t)BNT * 256];               // F = X * Wf^T
__device__ float g_cent[(size_t)BNT * 256];               // G = X * Wc^T
__device__ float g_xcat[(size_t)BNT * 512];               // concat [x1|x2|x3|x4]
__device__ float g_xx  [BNT];
__device__ float g_h5  [(size_t)BNT * 512];
__device__ float g_hmax[BATCH * 512];

// ---------------- squared row norms ----------------
__global__ void xx_kernel(const float* __restrict__ Aext, int asel, int lda, int offa, int C) {
    int p = blockIdx.x * blockDim.x + threadIdx.x;
    if (p >= BNT) return;
    const float* A = asel ? g_xcat : Aext;
    const float* r = A + (size_t)p * lda + offa;
    float s = 0.f;
    for (int c = 0; c < C; c++) s += r[c] * r[c];
    g_xx[p] = s;
}

// ---------------- pairwise neg-sqdist GEMM, symmetric: 128x128 tile, 8x8 micro ----------------
__global__ __launch_bounds__(256, 2)
void dist_gemm2(const float* __restrict__ Aext, int asel, int lda, int offa, int K) {
    __shared__ float As[16][136];
    __shared__ float Bs[16][136];
    int i0 = blockIdx.x * 128, j0 = blockIdx.y * 128;
    if (j0 < i0) return;
    const float* A = asel ? g_xcat : Aext;
    int base = blockIdx.z * NPTS;
    const float* Xb = A + (size_t)base * lda + offa;
    int tid = threadIdx.x, ty = tid >> 4, tx = tid & 15;
    float acc[8][8] = {};
    for (int k0 = 0; k0 < K; k0 += 16) {
        #pragma unroll
        for (int q = 0; q < 8; q++) {
            int e = q * 256 + tid;
            int r = e >> 4, kk = e & 15;
            int k = k0 + kk;
            As[kk][r] = (k < K) ? Xb[(size_t)(i0 + r) * lda + k] : 0.f;
            Bs[kk][r] = (k < K) ? Xb[(size_t)(j0 + r) * lda + k] : 0.f;
        }
        __syncthreads();
        #pragma unroll
        for (int kk = 0; kk < 16; kk++) {
            float4 a0 = *(const float4*)&As[kk][ty * 8];
            float4 a1 = *(const float4*)&As[kk][ty * 8 + 4];
            float4 b0 = *(const float4*)&Bs[kk][tx * 8];
            float4 b1 = *(const float4*)&Bs[kk][tx * 8 + 4];
            float a[8] = {a0.x, a0.y, a0.z, a0.w, a1.x, a1.y, a1.z, a1.w};
            float b[8] = {b0.x, b0.y, b0.z, b0.w, b1.x, b1.y, b1.z, b1.w};
            #pragma unroll
            for (int i = 0; i < 8; i++)
                #pragma unroll
                for (int j = 0; j < 8; j++) acc[i][j] += a[i] * b[j];
        }
        __syncthreads();
    }
    float* outb = g_dist + (size_t)blockIdx.z * NPTS * NPTS;
    float xi[8], xj[8];
    #pragma unroll
    for (int i = 0; i < 8; i++) xi[i] = g_xx[base + i0 + ty * 8 + i];
    #pragma unroll
    for (int j = 0; j < 8; j++) xj[j] = g_xx[base + j0 + tx * 8 + j];
    bool mirror = (j0 > i0);
    #pragma unroll
    for (int i = 0; i < 8; i++) {
        int gi = i0 + ty * 8 + i;
        #pragma unroll
        for (int j = 0; j < 8; j++) {
            int gj = j0 + tx * 8 + j;
            float v = 2.f * acc[i][j] - xi[i] - xj[j];
            outb[(size_t)gi * NPTS + gj] = v;
            if (mirror) outb[(size_t)gj * NPTS + gi] = v;
        }
    }
}

// ---------------- top-20 per row (warp per row, 20 argmax passes in smem) ----------------
__global__ __launch_bounds__(128)
void topk_kernel() {
    __shared__ float sd[4][NPTS];
    int w = threadIdx.x >> 5, lane = threadIdx.x & 31;
    int row = blockIdx.x * 4 + w;
    const float* dr = g_dist + (size_t)row * NPTS;
    for (int j = lane; j < NPTS; j += 32) sd[w][j] = dr[j];
    __syncwarp();
    int b = row >> 11;
    for (int t = 0; t < KNN; t++) {
        float bv = -CUDART_INF_F; int bi = 0;
        for (int j = lane; j < NPTS; j += 32) {
            float v = sd[w][j];
            if (v > bv || (v == bv && j < bi)) { bv = v; bi = j; }
        }
        #pragma unroll
        for (int off = 16; off; off >>= 1) {
            float ov = __shfl_xor_sync(0xffffffffu, bv, off);
            int   oi = __shfl_xor_sync(0xffffffffu, bi, off);
            if (ov > bv || (ov == bv && oi < bi)) { bv = ov; bi = oi; }
        }
        if (lane == 0) {
            g_nbr[(size_t)row * KNN + t] = (b << 11) + bi;
            sd[w][bi] = -CUDART_INF_F;
        }
        __syncwarp();
    }
}

// ---------------- plain GEMM: out[m,o] = sum_k A[m,k+offa] * W[o, offb+k] ----------------
// out_sel: 1 -> g_cent, 2 -> g_h5, 3 -> g_feat
template<int BN, int TN>
__global__ __launch_bounds__(256, 2)
void plain_gemm(const float* __restrict__ Aext, int asel, int lda, int offa,
                const float* __restrict__ W, int ldb, int offb,
                int out_sel, int ldo, int K,
                int epi, const float* __restrict__ gg, const float* __restrict__ bb) {
    __shared__ float As[16][136];
    __shared__ float Bs[16][BN + 8];
    const float* A = asel ? g_xcat : Aext;
    float* out = (out_sel == 1) ? g_cent : (out_sel == 2) ? g_h5 : g_feat;
    int m0 = blockIdx.x * 128;
    int o0 = blockIdx.y * BN;
    int tid = threadIdx.x, ty = tid >> 4, tx = tid & 15;
    float acc[8][TN] = {};
    for (int k0 = 0; k0 < K; k0 += 16) {
        #pragma unroll
        for (int q = 0; q < 8; q++) {
            int e = q * 256 + tid;
            int r = e >> 4, kk = e & 15;
            int k = k0 + kk;
            As[kk][r] = (k < K) ? A[(size_t)(m0 + r) * lda + offa + k] : 0.f;
        }
        #pragma unroll
        for (int q = 0; q < BN / 16; q++) {
            int e = q * 256 + tid;
            int r = e >> 4, kk = e & 15;
            int k = k0 + kk;
            Bs[kk][r] = (k < K) ? W[(size_t)(o0 + r) * ldb + offb + k] : 0.f;
        }
        __syncthreads();
        #pragma unroll
        for (int kk = 0; kk < 16; kk++) {
            float4 a0 = *(const float4*)&As[kk][ty * 8];
            float4 a1 = *(const float4*)&As[kk][ty * 8 + 4];
            float a[8] = {a0.x, a0.y, a0.z, a0.w, a1.x, a1.y, a1.z, a1.w};
            float b[TN];
            #pragma unroll
            for (int h = 0; h < TN / 4; h++) {
                float4 t = *(const float4*)&Bs[kk][tx * TN + h * 4];
                b[h * 4] = t.x; b[h * 4 + 1] = t.y; b[h * 4 + 2] = t.z; b[h * 4 + 3] = t.w;
            }
            #pragma unroll
            for (int i = 0; i < 8; i++)
                #pragma unroll
                for (int j = 0; j < TN; j++) acc[i][j] += a[i] * b[j];
        }
        __syncthreads();
    }
    float inv = rsqrtf(1.f + EPSV);
    #pragma unroll
    for (int i = 0; i < 8; i++) {
        int m = m0 + ty * 8 + i;
        #pragma unroll
        for (int j = 0; j < TN; j++) {
            int o = o0 + tx * TN + j;
            float v = acc[i][j];
            if (epi) {
                float s = gg[o] * inv;
                v = v * s + bb[o];
                v = (v >= 0.f) ? v : SLOPE * v;
            }
            out[(size_t)m * ldo + o] = v;
        }
    }
}

// ---------------- gather-max: x_out[p,o] = max_k lrelu((F[nbr]-F[p]+G[p])*s+b) ----------------
template<int O>
__global__ __launch_bounds__(O)
void gather_max(int offo, const float* __restrict__ gg, const float* __restrict__ bb) {
    __shared__ int s_nbr[KNN];
    int p = blockIdx.x;
    int o = threadIdx.x;
    if (o < KNN) s_nbr[o] = g_nbr[(size_t)p * KNN + o];
    __syncthreads();
    float fp = g_feat[(size_t)p * O + o];
    float c  = g_cent[(size_t)p * O + o] - fp;
    float s  = gg[o] * rsqrtf(1.f + EPSV);
    float bv = bb[o];
    float mx = -CUDART_INF_F;
    #pragma unroll
    for (int k = 0; k < KNN; k++) {
        float v = g_feat[(size_t)s_nbr[k] * O + o] + c;
        v = v * s + bv;
        v = (v >= 0.f) ? v : SLOPE * v;
        mx = fmaxf(mx, v);
    }
    g_xcat[(size_t)p * 512 + offo + o] = mx;
}

// ---------------- global max over n + write feat (4-way unrolled for MLP) ----------------
__global__ void maxn_kernel(float* __restrict__ out) {
    int gid = blockIdx.x * blockDim.x + threadIdx.x;
    if (gid >= BATCH * 512) return;
    int b = gid >> 9, o = gid & 511;
    const float* base = g_h5 + (size_t)b * NPTS * 512 + o;
    float m0 = -CUDART_INF_F, m1 = -CUDART_INF_F, m2 = -CUDART_INF_F, m3 = -CUDART_INF_F;
    for (int n = 0; n < NPTS; n += 4) {
        m0 = fmaxf(m0, base[(size_t)(n    ) * 512]);
        m1 = fmaxf(m1, base[(size_t)(n + 1) * 512]);
        m2 = fmaxf(m2, base[(size_t)(n + 2) * 512]);
        m3 = fmaxf(m3, base[(size_t)(n + 3) * 512]);
    }
    float mx = fmaxf(fmaxf(m0, m1), fmaxf(m2, m3));
    g_hmax[gid] = mx;
    out[gid] = mx;
}

// ---------------- embedding = h @ Wemb^T ----------------
__global__ void emb_kernel(const float* __restrict__ Wemb, float* __restrict__ out) {
    int gid = blockIdx.x * blockDim.x + threadIdx.x;
    if (gid >= BATCH * 256) return;
    int b = gid >> 8, oe = gid & 255;
    const float* h = g_hmax + b * 512;
    const float* w = Wemb + (size_t)oe * 512;
    float s = 0.f;
    for (int c = 0; c < 512; c++) s += h[c] * w[c];
    out[BATCH * 512 + gid] = s;
}

// ---------------- driver ----------------
static void run_layer(const float* Aext, int asel, int lda, int offa, int C,
                      const float* W, const float* gg, const float* bb,
                      int O, int offo) {
    xx_kernel<<<BNT / 256, 256>>>(Aext, asel, lda, offa, C);
    dist_gemm2<<<dim3(16, 16, 8), 256>>>(Aext, asel, lda, offa, C);
    topk_kernel<<<BNT / 4, 128>>>();
    // F = X * Wf^T  (edge-weight half, offb=0) -> g_feat ; G = X * Wc^T (offb=C) -> g_cent
    if (O == 64) {
        plain_gemm<64, 4><<<dim3(128, 1), 256>>>(Aext, asel, lda, offa,
                                                 W, 2 * C, 0, 3, O, C, 0, nullptr, nullptr);
        plain_gemm<64, 4><<<dim3(128, 1), 256>>>(Aext, asel, lda, offa,
                                                 W, 2 * C, C, 1, O, C, 0, nullptr, nullptr);
        gather_max<64><<<BNT, 64>>>(offo, gg, bb);
    } else if (O == 128) {
        plain_gemm<128, 8><<<dim3(128, 1), 256>>>(Aext, asel, lda, offa,
                                                  W, 2 * C, 0, 3, O, C, 0, nullptr, nullptr);
        plain_gemm<128, 8><<<dim3(128, 1), 256>>>(Aext, asel, lda, offa,
                                                  W, 2 * C, C, 1, O, C, 0, nullptr, nullptr);
        gather_max<128><<<BNT, 128>>>(offo, gg, bb);
    } else {
        plain_gemm<128, 8><<<dim3(128, 2), 256>>>(Aext, asel, lda, offa,
                                                  W, 2 * C, 0, 3, O, C, 0, nullptr, nullptr);
        plain_gemm<128, 8><<<dim3(128, 2), 256>>>(Aext, asel, lda, offa,
                                                  W, 2 * C, C, 1, O, C, 0, nullptr, nullptr);
        gather_max<256><<<BNT, 256>>>(offo, gg, bb);
    }
}

extern "C" void kernel_launch(void* const* d_in, const int* in_sizes, int n_in,
                              void* d_out, int out_size) {
    const float* x    = (const float*)d_in[0];
    const float* W1   = (const float*)d_in[1];
    const float* g1   = (const float*)d_in[2];
    const float* b1   = (const float*)d_in[3];
    const float* W2   = (const float*)d_in[4];
    const float* g2   = (const float*)d_in[5];
    const float* b2   = (const float*)d_in[6];
    const float* W3   = (const float*)d_in[7];
    const float* g3   = (const float*)d_in[8];
    const float* b3   = (const float*)d_in[9];
    const float* W4   = (const float*)d_in[10];
    const float* g4   = (const float*)d_in[11];
    const float* b4   = (const float*)d_in[12];
    const float* W5   = (const float*)d_in[13];
    const float* g5   = (const float*)d_in[14];
    const float* b5   = (const float*)d_in[15];
    const float* Wemb = (const float*)d_in[16];
    float* out = (float*)d_out;

    run_layer(x,       0, 3,   0,   3,   W1, g1, b1, 64,  0);
    run_layer(nullptr, 1, 512, 0,   64,  W2, g2, b2, 64,  64);
    run_layer(nullptr, 1, 512, 64,  64,  W3, g3, b3, 128, 128);
    run_layer(nullptr, 1, 512, 128, 128, W4, g4, b4, 256, 256);

    // W5 MLP with bn+lrelu epilogue -> g_h5
    plain_gemm<128, 8><<<dim3(128, 4), 256>>>(nullptr, 1, 512, 0,
                                              W5, 512, 0, 2, 512, 512, 1, g5, b5);
    maxn_kernel<<<16, 256>>>(out);
    emb_kernel<<<8, 256>>>(Wemb, out);
}